// round 1
// baseline (speedup 1.0000x reference)
#include <cuda_runtime.h>
#include <cstdint>

// Problem constants
#define B_ 128
#define T_ 2048
#define D_ 128
#define H_ 512
#define G_ 2048   // 4*H
#define K_ 640    // H + D
#define L_ 10

// Tiling
#define MT 4      // batch tiles (32 rows each)
#define NT 32     // packed-column tiles (64 cols each)
#define NBLK (MT*NT)
#define MTILE 32
#define NTILE 64
#define THREADS 256

// Smem layout (floats)
#define WS_STRIDE 644
#define AS_STRIDE 68
#define GS_STRIDE 68
#define OFF_WS 0
#define OFF_AS (NTILE*WS_STRIDE)                 // 41216
#define OFF_GS (OFF_AS + MTILE*AS_STRIDE)       // 43392
#define OFF_CS (OFF_GS + MTILE*GS_STRIDE)       // 45568
#define OFF_BS (OFF_CS + MTILE*16)              // 46080
#define SMEM_FLOATS (OFF_BS + NTILE)            // 46144
#define SMEM_BYTES (SMEM_FLOATS*4)              // 184576

// Device-global scratch (no cudaMalloc allowed)
__device__ float    g_Wpack[G_][K_];    // packed [W_hh | W_ih], tf32-rounded; row p = 4*j + gate
__device__ float    g_bpack[G_];
__device__ float    g_h[2][B_][H_];     // double-buffered hidden state (tf32-rounded fp32)
__device__ unsigned g_barcnt[MT*32];    // one counter per batch group, 128B apart

__device__ __forceinline__ float to_tf32(float x){
    uint32_t u; asm("cvt.rna.tf32.f32 %0, %1;" : "=r"(u) : "f"(x));
    return __uint_as_float(u);
}
__device__ __forceinline__ float sigm(float x){ return 1.0f/(1.0f + __expf(-x)); }

// ---------------- setup kernels ----------------
__global__ void pack_kernel(const float* __restrict__ W_ih,
                            const float* __restrict__ W_hh,
                            const float* __restrict__ b){
    int p = blockIdx.x;           // 0..2047
    int j = p >> 2;               // h index
    int g = p & 3;                // gate (i,f,g,o)
    int src = g*H_ + j;
    for (int k = threadIdx.x; k < K_; k += blockDim.x){
        float v = (k < H_) ? W_hh[src*H_ + k] : W_ih[src*D_ + (k - H_)];
        g_Wpack[p][k] = to_tf32(v);
    }
    if (threadIdx.x == 0) g_bpack[p] = b[src];
}

__global__ void init_kernel(){
    int i = blockIdx.x*blockDim.x + threadIdx.x;
    if (i < B_*H_) ((float*)g_h)[i] = 0.0f;      // zero g_h[0]
    if (i < MT*32) g_barcnt[i] = 0u;
}

// ---------------- group barrier (monotonic counter) ----------------
__device__ __forceinline__ void group_barrier(int m, int t){
    __syncthreads();
    if (threadIdx.x == 0){
        __threadfence();
        atomicAdd(&g_barcnt[m*32], 1u);
        unsigned target = (unsigned)(t + 1) * NT;
        while (*(volatile unsigned*)&g_barcnt[m*32] < target) { __nanosleep(32); }
        __threadfence();
    }
    __syncthreads();
}

// ---------------- main persistent scan kernel ----------------
__global__ void __launch_bounds__(THREADS, 1) lstm_scan(const float* __restrict__ x){
    extern __shared__ float sm[];
    float* Ws = sm + OFF_WS;   // [64][644]  weight slice (tf32)
    float* As = sm + OFF_AS;   // [32][68]   A chunk
    float* Gs = sm + OFF_GS;   // [32][68]   gates tile
    float* cs = sm + OFF_CS;   // [32][16]   cell state
    float* bs = sm + OFF_BS;   // [64]       bias slice

    const int tid = threadIdx.x;
    const int nb_ = blockIdx.x % NT;
    const int mb_ = blockIdx.x / NT;
    const int m0 = mb_ * MTILE;
    const int p0 = nb_ * NTILE;
    const int j0 = nb_ * 16;

    // Load weight slice once (64 rows x 640 cols, contiguous in g_Wpack)
    {
        const float4* src = (const float4*)&g_Wpack[p0][0];
        for (int i = tid; i < (NTILE*K_)/4; i += THREADS){
            float4 v = src[i];
            int idx = i*4; int r = idx/K_, c = idx%K_;
            *(float4*)&Ws[r*WS_STRIDE + c] = v;
        }
    }
    if (tid < NTILE) bs[tid] = g_bpack[p0 + tid];
    for (int i = tid; i < MTILE*16; i += THREADS) cs[i] = 0.0f;
    __syncthreads();

    const int lane = tid & 31, warp = tid >> 5;
    const int wm = warp >> 2;          // 0..1 : m offset 16*wm
    const int wn = warp & 3;           // 0..3 : n offset 16*wn
    const int grp = lane >> 2, tig = lane & 3;

    for (int t = 0; t < T_; ++t){
        const int rb = t & 1;
        float acc0[4] = {0.f,0.f,0.f,0.f};
        float acc1[4] = {0.f,0.f,0.f,0.f};
        const float* hsrc = &g_h[rb][m0][0];

        #pragma unroll 1
        for (int ch = 0; ch < 10; ++ch){
            // ---- load A chunk: rows = 32 batch, cols = 64 K values ----
            {
                int c4 = (tid & 15) * 4;
                int r = tid >> 4;
                #pragma unroll
                for (int rr = 0; rr < 2; ++rr){
                    float4 v;
                    if (ch < 8){
                        v = __ldcg((const float4*)(hsrc + r*H_ + ch*64 + c4));
                    } else {
                        const float* xp = x + ((size_t)(m0 + r)*T_ + t)*D_ + (ch-8)*64 + c4;
                        v = *(const float4*)xp;
                        v.x = to_tf32(v.x); v.y = to_tf32(v.y);
                        v.z = to_tf32(v.z); v.w = to_tf32(v.w);
                    }
                    *(float4*)&As[r*AS_STRIDE + c4] = v;
                    r += 16;
                }
            }
            __syncthreads();
            // ---- 8 k-steps of mma.m16n8k8 tf32 ----
            const int kbase = ch*64;
            #pragma unroll
            for (int ks = 0; ks < 8; ++ks){
                const int k = ks*8;
                uint32_t a0 = __float_as_uint(As[(wm*16+grp  )*AS_STRIDE + k + tig    ]);
                uint32_t a1 = __float_as_uint(As[(wm*16+grp+8)*AS_STRIDE + k + tig    ]);
                uint32_t a2 = __float_as_uint(As[(wm*16+grp  )*AS_STRIDE + k + tig + 4]);
                uint32_t a3 = __float_as_uint(As[(wm*16+grp+8)*AS_STRIDE + k + tig + 4]);
                {
                    int p = wn*16 + grp;
                    uint32_t b0 = __float_as_uint(Ws[p*WS_STRIDE + kbase + k + tig    ]);
                    uint32_t b1 = __float_as_uint(Ws[p*WS_STRIDE + kbase + k + tig + 4]);
                    asm volatile("mma.sync.aligned.m16n8k8.row.col.f32.tf32.tf32.f32 "
                        "{%0,%1,%2,%3}, {%4,%5,%6,%7}, {%8,%9}, {%0,%1,%2,%3};\n"
                        : "+f"(acc0[0]), "+f"(acc0[1]), "+f"(acc0[2]), "+f"(acc0[3])
                        : "r"(a0),"r"(a1),"r"(a2),"r"(a3), "r"(b0),"r"(b1));
                }
                {
                    int p = wn*16 + 8 + grp;
                    uint32_t b0 = __float_as_uint(Ws[p*WS_STRIDE + kbase + k + tig    ]);
                    uint32_t b1 = __float_as_uint(Ws[p*WS_STRIDE + kbase + k + tig + 4]);
                    asm volatile("mma.sync.aligned.m16n8k8.row.col.f32.tf32.tf32.f32 "
                        "{%0,%1,%2,%3}, {%4,%5,%6,%7}, {%8,%9}, {%0,%1,%2,%3};\n"
                        : "+f"(acc1[0]), "+f"(acc1[1]), "+f"(acc1[2]), "+f"(acc1[3])
                        : "r"(a0),"r"(a1),"r"(a2),"r"(a3), "r"(b0),"r"(b1));
                }
            }
            __syncthreads();
        }

        // ---- scatter accumulators to gates tile ----
        {
            int r0 = (wm*16 + grp)*GS_STRIDE, r1 = (wm*16 + grp + 8)*GS_STRIDE;
            int c0 = wn*16 + 2*tig, c1 = wn*16 + 8 + 2*tig;
            Gs[r0 + c0    ] = acc0[0];  Gs[r0 + c0 + 1] = acc0[1];
            Gs[r1 + c0    ] = acc0[2];  Gs[r1 + c0 + 1] = acc0[3];
            Gs[r0 + c1    ] = acc1[0];  Gs[r0 + c1 + 1] = acc1[1];
            Gs[r1 + c1    ] = acc1[2];  Gs[r1 + c1 + 1] = acc1[3];
        }
        __syncthreads();

        // ---- elementwise LSTM cell update: 512 (b, j) pairs per CTA ----
        const int wbuf = rb ^ 1;
        #pragma unroll
        for (int it = 0; it < 2; ++it){
            int idx = tid + it*THREADS;
            int b  = idx >> 4;
            int jj = idx & 15;
            float gi = Gs[b*GS_STRIDE + 4*jj + 0] + bs[4*jj + 0];
            float gf = Gs[b*GS_STRIDE + 4*jj + 1] + bs[4*jj + 1];
            float gg = Gs[b*GS_STRIDE + 4*jj + 2] + bs[4*jj + 2];
            float go = Gs[b*GS_STRIDE + 4*jj + 3] + bs[4*jj + 3];
            float c_old = cs[b*16 + jj];
            float cn = sigm(gf)*c_old + sigm(gi)*tanhf(gg);
            float hn = sigm(go)*tanhf(cn);
            cs[b*16 + jj] = cn;
            g_h[wbuf][m0 + b][j0 + jj] = to_tf32(hn);
        }

        group_barrier(mb_, t);
    }
}

// ---------------- output head: logits + softmax ----------------
__global__ void out_kernel(const float* __restrict__ W_out, float* __restrict__ out){
    int b = blockIdx.x;      // 128 blocks
    int lane = threadIdx.x;  // 32 threads
    float acc[L_];
    #pragma unroll
    for (int l = 0; l < L_; ++l) acc[l] = 0.0f;
    for (int k = lane; k < H_; k += 32){
        float hv = g_h[0][b][k];   // T even -> final h lives in buffer 0
        #pragma unroll
        for (int l = 0; l < L_; ++l) acc[l] += hv * __ldg(&W_out[l*H_ + k]);
    }
    #pragma unroll
    for (int l = 0; l < L_; ++l){
        #pragma unroll
        for (int o = 16; o; o >>= 1) acc[l] += __shfl_xor_sync(0xffffffffu, acc[l], o);
    }
    if (lane == 0){
        float mx = acc[0];
        #pragma unroll
        for (int l = 1; l < L_; ++l) mx = fmaxf(mx, acc[l]);
        float s = 0.0f;
        #pragma unroll
        for (int l = 0; l < L_; ++l){ acc[l] = expf(acc[l] - mx); s += acc[l]; }
        float inv = 1.0f / s;
        #pragma unroll
        for (int l = 0; l < L_; ++l) out[b*L_ + l] = acc[l] * inv;
    }
}

// ---------------- launch ----------------
extern "C" void kernel_launch(void* const* d_in, const int* in_sizes, int n_in,
                              void* d_out, int out_size){
    const float* x     = (const float*)d_in[0];
    const float* W_ih  = (const float*)d_in[1];
    const float* W_hh  = (const float*)d_in[2];
    const float* b     = (const float*)d_in[3];
    const float* W_out = (const float*)d_in[4];

    cudaFuncSetAttribute(lstm_scan, cudaFuncAttributeMaxDynamicSharedMemorySize, SMEM_BYTES);

    pack_kernel<<<G_, 256>>>(W_ih, W_hh, b);
    init_kernel<<<256, 256>>>();
    lstm_scan<<<NBLK, THREADS, SMEM_BYTES>>>(x);
    out_kernel<<<B_, 32>>>(W_out, (float*)d_out);
}

// round 3
// speedup vs baseline: 2.1418x; 2.1418x over previous
#include <cuda_runtime.h>
#include <cuda_bf16.h>
#include <cstdint>

// Problem constants
#define B_ 128
#define T_ 2048
#define D_ 128
#define H_ 512
#define G_ 2048   // 4*H
#define K_ 640    // H + D
#define L_ 10

// Tiling: 4 batch groups x 32 column-tile CTAs; 8 warps split K (80 each)
#define MT 4
#define NT 32
#define NBLK (MT*NT)
#define THREADS 256

// Smem strides (bf16 elements)
#define WS_STR 648
#define AS_STR 648

// Smem byte offsets
#define OFF_WS 0
#define OFF_AS (64*WS_STR*2)            // 82944
#define OFF_GS (OFF_AS + 32*AS_STR*2)   // 124416 : 8 slabs of [32][68] fp32
#define OFF_CS (OFF_GS + 8*32*68*4)     // 194048 : fp32 cell [32][16]
#define OFF_BS (OFF_CS + 32*16*4)       // 196096 : fp32 bias [64]
#define SMEM_BYTES (OFF_BS + 64*4)      // 196352

// Device-global scratch — ALL explicitly aligned (R2 lesson: bf16 globals
// have natural alignment 2; vector access without __align__ is UB).
__device__ __align__(256) __nv_bfloat16 g_Wpk[G_][K_];
__device__ __align__(256) float         g_bpk[G_];
__device__ __align__(256) __nv_bfloat16 g_h[2][B_][H_];
__device__ __align__(256) __nv_bfloat16 g_xB[(size_t)B_*T_*D_];
__device__ __align__(256) unsigned      g_barcnt[MT*32];

__device__ __forceinline__ float sigm(float x){ return 1.0f/(1.0f + __expf(-x)); }

// ---------------- setup kernels ----------------
__global__ void xconv_kernel(const float* __restrict__ x){
    size_t i = (size_t)blockIdx.x*blockDim.x + threadIdx.x;   // over N/4
    float4 v = ((const float4*)x)[i];
    __nv_bfloat162* dst = (__nv_bfloat162*)g_xB;
    dst[2*i]   = __floats2bfloat162_rn(v.x, v.y);
    dst[2*i+1] = __floats2bfloat162_rn(v.z, v.w);
}

__global__ void pack_kernel(const float* __restrict__ W_ih,
                            const float* __restrict__ W_hh,
                            const float* __restrict__ b){
    int p = blockIdx.x;           // 0..2047
    int j = p >> 2;
    int g = p & 3;
    int src = g*H_ + j;
    for (int k = threadIdx.x; k < K_; k += blockDim.x){
        float v = (k < H_) ? W_hh[src*H_ + k] : W_ih[src*D_ + (k - H_)];
        g_Wpk[p][k] = __float2bfloat16_rn(v);
    }
    if (threadIdx.x == 0) g_bpk[p] = b[src];
}

__global__ void init_kernel(){
    int i = blockIdx.x*blockDim.x + threadIdx.x;
    if (i < B_*H_) ((__nv_bfloat16*)g_h)[i] = __float2bfloat16(0.0f);
    if (i < MT*32) g_barcnt[i] = 0u;
}

// ---------------- main persistent scan kernel ----------------
__global__ void __launch_bounds__(THREADS, 1) lstm_scan(){
    extern __shared__ char smc[];
    const uint32_t sb = (uint32_t)__cvta_generic_to_shared(smc);
    float* GsAll = (float*)(smc + OFF_GS);
    float* cs    = (float*)(smc + OFF_CS);
    float* bs    = (float*)(smc + OFF_BS);

    const int tid = threadIdx.x;
    const int nb_ = blockIdx.x % NT;
    const int mb_ = blockIdx.x / NT;
    const int m0 = mb_ * 32;
    const int p0 = nb_ * 64;
    const int j0 = nb_ * 16;

    // Load weight slice once: 64 rows x 640 bf16 (80 float4 per row)
    {
        const float4* src = (const float4*)&g_Wpk[p0][0];
        for (int i = tid; i < 64*80; i += THREADS){
            int r = i/80, c = i%80;
            *(float4*)(smc + OFF_WS + r*WS_STR*2 + c*16) = __ldcg(src + (size_t)r*80 + c);
        }
    }
    if (tid < 64) bs[tid] = g_bpk[p0 + tid];
    for (int i = tid; i < 32*16; i += THREADS) cs[i] = 0.0f;
    __syncthreads();

    const int lane = tid & 31, warp = tid >> 5;
    const int grp = lane >> 2, tig = lane & 3;
    const int ks = warp;          // this warp's k-chunk (80 wide)

    // ldmatrix per-lane base addresses (byte addresses in shared space)
    uint32_t aBase[2], bBase[4];
    #pragma unroll
    for (int mh = 0; mh < 2; ++mh)
        aBase[mh] = sb + OFF_AS +
            (uint32_t)(((mh*16 + (lane & 15))*AS_STR + (lane >> 4)*8)*2);
    #pragma unroll
    for (int nn = 0; nn < 4; ++nn)
        bBase[nn] = sb + OFF_WS +
            (uint32_t)(((nn*16 + ((lane >> 4) << 3) + (lane & 7))*WS_STR + ((lane >> 3) & 1)*8)*2);

    for (int t = 0; t < T_; ++t){
        // ---- bulk load A tile: h part (32x512) + x part (32x128), bf16 ----
        {
            const __nv_bfloat16* hsrc = &g_h[t & 1][m0][0];
            #pragma unroll
            for (int i = 0; i < 8; ++i){
                int s = tid + i*THREADS;
                int r = s >> 6, c = s & 63;
                float4 v = __ldcg((const float4*)(hsrc + r*H_ + c*8));
                *(float4*)(smc + OFF_AS + r*AS_STR*2 + c*16) = v;
            }
            const __nv_bfloat16* xsrc = g_xB + ((size_t)m0*T_ + t)*D_;
            #pragma unroll
            for (int i = 0; i < 2; ++i){
                int s = tid + i*THREADS;
                int r = s >> 4, c = s & 15;
                float4 v = __ldcg((const float4*)(xsrc + (size_t)r*T_*D_ + c*8));
                *(float4*)(smc + OFF_AS + r*AS_STR*2 + 1024 + c*16) = v;
            }
        }
        __syncthreads();

        // ---- MMA: this warp does m32 x n64 x k80 (5 k16-steps) ----
        float acc[2][8][4] = {};
        #pragma unroll
        for (int q = 0; q < 5; ++q){
            const uint32_t kb = (uint32_t)((ks*5 + q)*32);   // byte offset along row
            uint32_t a[2][4], bfr[4][4];
            #pragma unroll
            for (int mh = 0; mh < 2; ++mh)
                asm volatile("ldmatrix.sync.aligned.m8n8.x4.shared.b16 {%0,%1,%2,%3}, [%4];"
                    : "=r"(a[mh][0]),"=r"(a[mh][1]),"=r"(a[mh][2]),"=r"(a[mh][3])
                    : "r"(aBase[mh] + kb));
            #pragma unroll
            for (int nn = 0; nn < 4; ++nn)
                asm volatile("ldmatrix.sync.aligned.m8n8.x4.shared.b16 {%0,%1,%2,%3}, [%4];"
                    : "=r"(bfr[nn][0]),"=r"(bfr[nn][1]),"=r"(bfr[nn][2]),"=r"(bfr[nn][3])
                    : "r"(bBase[nn] + kb));
            #pragma unroll
            for (int mh = 0; mh < 2; ++mh)
                #pragma unroll
                for (int nn = 0; nn < 4; ++nn){
                    float* A0 = acc[mh][2*nn];
                    float* A1 = acc[mh][2*nn + 1];
                    asm volatile("mma.sync.aligned.m16n8k16.row.col.f32.bf16.bf16.f32 "
                        "{%0,%1,%2,%3}, {%4,%5,%6,%7}, {%8,%9}, {%0,%1,%2,%3};"
                        : "+f"(A0[0]),"+f"(A0[1]),"+f"(A0[2]),"+f"(A0[3])
                        : "r"(a[mh][0]),"r"(a[mh][1]),"r"(a[mh][2]),"r"(a[mh][3]),
                          "r"(bfr[nn][0]),"r"(bfr[nn][1]));
                    asm volatile("mma.sync.aligned.m16n8k16.row.col.f32.bf16.bf16.f32 "
                        "{%0,%1,%2,%3}, {%4,%5,%6,%7}, {%8,%9}, {%0,%1,%2,%3};"
                        : "+f"(A1[0]),"+f"(A1[1]),"+f"(A1[2]),"+f"(A1[3])
                        : "r"(a[mh][0]),"r"(a[mh][1]),"r"(a[mh][2]),"r"(a[mh][3]),
                          "r"(bfr[nn][2]),"r"(bfr[nn][3]));
                }
        }

        // ---- scatter partial gates to this warp's slab ----
        {
            float* Gw = GsAll + warp*(32*68);
            #pragma unroll
            for (int mh = 0; mh < 2; ++mh){
                int r0 = (mh*16 + grp)*68, r1 = r0 + 8*68;
                #pragma unroll
                for (int nb8 = 0; nb8 < 8; ++nb8){
                    int c = nb8*8 + 2*tig;
                    float* A = acc[mh][nb8];
                    Gw[r0 + c] = A[0];  Gw[r0 + c + 1] = A[1];
                    Gw[r1 + c] = A[2];  Gw[r1 + c + 1] = A[3];
                }
            }
        }
        __syncthreads();

        // ---- reduce 8 k-partials + LSTM cell update (512 pairs) ----
        const int wbuf = (t + 1) & 1;
        #pragma unroll
        for (int it = 0; it < 2; ++it){
            int idx = tid + it*THREADS;
            int b  = idx >> 4;
            int jj = idx & 15;
            float gi = bs[4*jj + 0], gf = bs[4*jj + 1];
            float gg = bs[4*jj + 2], go = bs[4*jj + 3];
            #pragma unroll
            for (int w = 0; w < 8; ++w){
                float4 v = *(const float4*)&GsAll[w*(32*68) + b*68 + 4*jj];
                gi += v.x; gf += v.y; gg += v.z; go += v.w;
            }
            float c_old = cs[b*16 + jj];
            float cn = sigm(gf)*c_old + sigm(gi)*tanhf(gg);
            float hn = sigm(go)*tanhf(cn);
            cs[b*16 + jj] = cn;
            g_h[wbuf][m0 + b][j0 + jj] = __float2bfloat16_rn(hn);
        }

        // ---- group barrier (R1-proven: volatile spin + nanosleep) ----
        __syncthreads();
        if (tid == 0){
            __threadfence();
            atomicAdd(&g_barcnt[mb_*32], 1u);
            unsigned target = (unsigned)(t + 1) * NT;
            while (*(volatile unsigned*)&g_barcnt[mb_*32] < target) { __nanosleep(32); }
            __threadfence();
        }
        __syncthreads();
    }
}

// ---------------- output head: logits + softmax ----------------
__global__ void out_kernel(const float* __restrict__ W_out, float* __restrict__ out){
    int b = blockIdx.x;
    int lane = threadIdx.x;
    float acc[L_];
    #pragma unroll
    for (int l = 0; l < L_; ++l) acc[l] = 0.0f;
    for (int k = lane; k < H_; k += 32){
        float hv = __bfloat162float(g_h[0][b][k]);   // T even -> final h in buffer 0
        #pragma unroll
        for (int l = 0; l < L_; ++l) acc[l] += hv * __ldg(&W_out[l*H_ + k]);
    }
    #pragma unroll
    for (int l = 0; l < L_; ++l){
        #pragma unroll
        for (int o = 16; o; o >>= 1) acc[l] += __shfl_xor_sync(0xffffffffu, acc[l], o);
    }
    if (lane == 0){
        float mx = acc[0];
        #pragma unroll
        for (int l = 1; l < L_; ++l) mx = fmaxf(mx, acc[l]);
        float s = 0.0f;
        #pragma unroll
        for (int l = 0; l < L_; ++l){ acc[l] = expf(acc[l] - mx); s += acc[l]; }
        float inv = 1.0f / s;
        #pragma unroll
        for (int l = 0; l < L_; ++l) out[b*L_ + l] = acc[l] * inv;
    }
}

// ---------------- launch ----------------
extern "C" void kernel_launch(void* const* d_in, const int* in_sizes, int n_in,
                              void* d_out, int out_size){
    const float* x     = (const float*)d_in[0];
    const float* W_ih  = (const float*)d_in[1];
    const float* W_hh  = (const float*)d_in[2];
    const float* b     = (const float*)d_in[3];
    const float* W_out = (const float*)d_in[4];

    cudaFuncSetAttribute(lstm_scan, cudaFuncAttributeMaxDynamicSharedMemorySize, SMEM_BYTES);

    xconv_kernel<<<(B_*T_*D_/4)/256, 256>>>(x);
    pack_kernel<<<G_, 256>>>(W_ih, W_hh, b);
    init_kernel<<<256, 256>>>();
    lstm_scan<<<NBLK, THREADS, SMEM_BYTES>>>();
    out_kernel<<<B_, 32>>>(W_out, (float*)d_out);
}

// round 6
// speedup vs baseline: 2.3623x; 1.1030x over previous
#include <cuda_runtime.h>
#include <cuda_bf16.h>
#include <cstdint>

// Problem constants
#define B_ 128
#define T_ 2048
#define D_ 128
#define H_ 512
#define G_ 2048   // 4*H
#define K_ 640    // H + D
#define L_ 10

// Tiling: 4 batch groups x 32 column-tile CTAs.
// Within a CTA: 8 warps = 4 k-chunks (160) x 2 n-halves (32).
#define MT 4
#define NT 32
#define NBLK (MT*NT)
#define THREADS 256

// Smem strides (bf16 elements)
#define WS_STR 648
#define AS_STR 648

// Smem byte offsets
#define OFF_WS 0
#define OFF_AS (64*WS_STR*2)            // 82944
#define OFF_GS (OFF_AS + 32*AS_STR*2)   // 124416 : 4 slabs of [32][68] fp32
#define OFF_CS (OFF_GS + 4*32*68*4)     // 159232 : fp32 cell [32][16]
#define OFF_BS (OFF_CS + 32*16*4)       // 161280 : fp32 bias [64]
#define SMEM_BYTES (OFF_BS + 64*4)      // 161536

// Device-global scratch (all explicitly aligned — R2 lesson)
__device__ __align__(256) __nv_bfloat16 g_Wpk[G_][K_];
__device__ __align__(256) float         g_bpk[G_];
__device__ __align__(256) __nv_bfloat16 g_h[2][B_][H_];
__device__ __align__(256) __nv_bfloat16 g_xB[(size_t)B_*T_*D_];
__device__ __align__(256) unsigned      g_barcnt[MT*32];

__device__ __forceinline__ float tanhapx(float x){
    float y; asm("tanh.approx.f32 %0, %1;" : "=f"(y) : "f"(x)); return y;
}
__device__ __forceinline__ float sigm(float x){
    return fmaf(tanhapx(0.5f*x), 0.5f, 0.5f);
}

// ---------------- setup kernels ----------------
__global__ void xconv_kernel(const float* __restrict__ x){
    size_t i = (size_t)blockIdx.x*blockDim.x + threadIdx.x;
    float4 v = ((const float4*)x)[i];
    __nv_bfloat162* dst = (__nv_bfloat162*)g_xB;
    dst[2*i]   = __floats2bfloat162_rn(v.x, v.y);
    dst[2*i+1] = __floats2bfloat162_rn(v.z, v.w);
}

__global__ void pack_kernel(const float* __restrict__ W_ih,
                            const float* __restrict__ W_hh,
                            const float* __restrict__ b){
    int p = blockIdx.x;
    int j = p >> 2;
    int g = p & 3;
    int src = g*H_ + j;
    for (int k = threadIdx.x; k < K_; k += blockDim.x){
        float v = (k < H_) ? W_hh[src*H_ + k] : W_ih[src*D_ + (k - H_)];
        g_Wpk[p][k] = __float2bfloat16_rn(v);
    }
    if (threadIdx.x == 0) g_bpk[p] = b[src];
}

__global__ void init_kernel(){
    int i = blockIdx.x*blockDim.x + threadIdx.x;
    if (i < B_*H_) ((__nv_bfloat16*)g_h)[i] = __float2bfloat16(0.0f);
    if (i < MT*32) g_barcnt[i] = 0u;
}

// ---------------- main persistent scan kernel ----------------
__global__ void __launch_bounds__(THREADS, 1) lstm_scan(){
    extern __shared__ char smc[];
    const uint32_t sb = (uint32_t)__cvta_generic_to_shared(smc);
    float* Gs = (float*)(smc + OFF_GS);
    float* cs = (float*)(smc + OFF_CS);
    float* bs = (float*)(smc + OFF_BS);

    const int tid = threadIdx.x;
    const int nb_ = blockIdx.x % NT;
    const int mb_ = blockIdx.x / NT;
    const int m0 = mb_ * 32;
    const int p0 = nb_ * 64;
    const int j0 = nb_ * 16;

    // Load weight slice once: 64 rows x 640 bf16 (80 float4 per row)
    {
        const float4* src = (const float4*)&g_Wpk[p0][0];
        for (int i = tid; i < 64*80; i += THREADS){
            int r = i/80, c = i%80;
            *(float4*)(smc + OFF_WS + r*WS_STR*2 + c*16) = __ldcg(src + (size_t)r*80 + c);
        }
    }
    if (tid < 64) bs[tid] = g_bpk[p0 + tid];
    for (int i = tid; i < 32*16; i += THREADS) cs[i] = 0.0f;
    __syncthreads();

    const int lane = tid & 31, warp = tid >> 5;
    const int grp = lane >> 2, tig = lane & 3;
    const int wk  = warp & 3;        // k-chunk (160 wide = 10 q-steps)
    const int wn2 = warp >> 2;       // n-half (32 cols)

    // ---- B (weight) fragments: load ONCE into registers, keep for all T steps ----
    uint32_t bf[10][2][4];
    {
        const int brow = ((lane >> 4) << 3) + (lane & 7);
        const int bcol8 = ((lane >> 3) & 1) * 8;
        #pragma unroll
        for (int q = 0; q < 10; ++q)
            #pragma unroll
            for (int nn = 0; nn < 2; ++nn){
                uint32_t addr = sb + OFF_WS +
                    (uint32_t)(((wn2*32 + nn*16 + brow)*WS_STR + wk*160 + q*16 + bcol8)*2);
                asm volatile("ldmatrix.sync.aligned.m8n8.x4.shared.b16 {%0,%1,%2,%3}, [%4];"
                    : "=r"(bf[q][nn][0]),"=r"(bf[q][nn][1]),"=r"(bf[q][nn][2]),"=r"(bf[q][nn][3])
                    : "r"(addr));
            }
    }

    // A-fragment ldmatrix base addresses
    uint32_t aBase[2];
    #pragma unroll
    for (int mh = 0; mh < 2; ++mh)
        aBase[mh] = sb + OFF_AS +
            (uint32_t)(((mh*16 + (lane & 15))*AS_STR + (lane >> 4)*8)*2);

    for (int t = 0; t < T_; ++t){
        // ---- bulk load A tile: h part (32x512) + x part (32x128), bf16 ----
        {
            const __nv_bfloat16* hsrc = &g_h[t & 1][m0][0];
            #pragma unroll
            for (int i = 0; i < 8; ++i){
                int s = tid + i*THREADS;
                int r = s >> 6, c = s & 63;
                float4 v = __ldcg((const float4*)(hsrc + r*H_ + c*8));
                *(float4*)(smc + OFF_AS + r*AS_STR*2 + c*16) = v;
            }
            const __nv_bfloat16* xsrc = g_xB + ((size_t)m0*T_ + t)*D_;
            #pragma unroll
            for (int i = 0; i < 2; ++i){
                int s = tid + i*THREADS;
                int r = s >> 4, c = s & 15;
                float4 v = __ldcg((const float4*)(xsrc + (size_t)r*T_*D_ + c*8));
                *(float4*)(smc + OFF_AS + r*AS_STR*2 + 1024 + c*16) = v;
            }
        }
        __syncthreads();

        // ---- MMA: m32 x n32 x k160 per warp; A frags double-buffered ----
        float acc[2][4][4] = {};
        {
            const uint32_t kbase = (uint32_t)(wk*320);
            uint32_t a[2][2][4];
            #pragma unroll
            for (int mh = 0; mh < 2; ++mh)
                asm volatile("ldmatrix.sync.aligned.m8n8.x4.shared.b16 {%0,%1,%2,%3}, [%4];"
                    : "=r"(a[0][mh][0]),"=r"(a[0][mh][1]),"=r"(a[0][mh][2]),"=r"(a[0][mh][3])
                    : "r"(aBase[mh] + kbase));
            #pragma unroll
            for (int q = 0; q < 10; ++q){
                const int cur = q & 1, nxt = cur ^ 1;
                if (q < 9){
                    #pragma unroll
                    for (int mh = 0; mh < 2; ++mh)
                        asm volatile("ldmatrix.sync.aligned.m8n8.x4.shared.b16 {%0,%1,%2,%3}, [%4];"
                            : "=r"(a[nxt][mh][0]),"=r"(a[nxt][mh][1]),
                              "=r"(a[nxt][mh][2]),"=r"(a[nxt][mh][3])
                            : "r"(aBase[mh] + kbase + (q+1)*32));
                }
                #pragma unroll
                for (int mh = 0; mh < 2; ++mh)
                    #pragma unroll
                    for (int nn = 0; nn < 2; ++nn){
                        float* A0 = acc[mh][2*nn];
                        float* A1 = acc[mh][2*nn + 1];
                        asm("mma.sync.aligned.m16n8k16.row.col.f32.bf16.bf16.f32 "
                            "{%0,%1,%2,%3}, {%4,%5,%6,%7}, {%8,%9}, {%0,%1,%2,%3};"
                            : "+f"(A0[0]),"+f"(A0[1]),"+f"(A0[2]),"+f"(A0[3])
                            : "r"(a[cur][mh][0]),"r"(a[cur][mh][1]),
                              "r"(a[cur][mh][2]),"r"(a[cur][mh][3]),
                              "r"(bf[q][nn][0]),"r"(bf[q][nn][1]));
                        asm("mma.sync.aligned.m16n8k16.row.col.f32.bf16.bf16.f32 "
                            "{%0,%1,%2,%3}, {%4,%5,%6,%7}, {%8,%9}, {%0,%1,%2,%3};"
                            : "+f"(A1[0]),"+f"(A1[1]),"+f"(A1[2]),"+f"(A1[3])
                            : "r"(a[cur][mh][0]),"r"(a[cur][mh][1]),
                              "r"(a[cur][mh][2]),"r"(a[cur][mh][3]),
                              "r"(bf[q][nn][2]),"r"(bf[q][nn][3]));
                    }
            }
        }

        // ---- scatter partial gates to slab[wk] ----
        {
            float* Gw = Gs + wk*(32*68);
            #pragma unroll
            for (int mh = 0; mh < 2; ++mh){
                int r0 = (mh*16 + grp)*68, r1 = r0 + 8*68;
                #pragma unroll
                for (int nn = 0; nn < 2; ++nn)
                    #pragma unroll
                    for (int hi = 0; hi < 2; ++hi){
                        int c = wn2*32 + nn*16 + hi*8 + 2*tig;
                        float* A = acc[mh][2*nn + hi];
                        *(float2*)&Gw[r0 + c] = make_float2(A[0], A[1]);
                        *(float2*)&Gw[r1 + c] = make_float2(A[2], A[3]);
                    }
            }
        }
        __syncthreads();

        // ---- reduce 4 k-partials + LSTM cell update (2 pairs per thread) ----
        const int wbuf = (t + 1) & 1;
        {
            int b  = tid >> 3;
            int jp = tid & 7;               // jj pair: 2*jp, 2*jp+1
            float4 s0 = *(const float4*)&bs[8*jp];
            float4 s1 = *(const float4*)&bs[8*jp + 4];
            #pragma unroll
            for (int w = 0; w < 4; ++w){
                const float* base = &Gs[w*(32*68) + b*68 + 8*jp];
                float4 v0 = *(const float4*)(base);
                float4 v1 = *(const float4*)(base + 4);
                s0.x += v0.x; s0.y += v0.y; s0.z += v0.z; s0.w += v0.w;
                s1.x += v1.x; s1.y += v1.y; s1.z += v1.z; s1.w += v1.w;
            }
            float c0 = cs[b*16 + 2*jp], c1 = cs[b*16 + 2*jp + 1];
            float cn0 = sigm(s0.y)*c0 + sigm(s0.x)*tanhapx(s0.z);
            float cn1 = sigm(s1.y)*c1 + sigm(s1.x)*tanhapx(s1.z);
            float hn0 = sigm(s0.w)*tanhapx(cn0);
            float hn1 = sigm(s1.w)*tanhapx(cn1);
            cs[b*16 + 2*jp]     = cn0;
            cs[b*16 + 2*jp + 1] = cn1;
            __nv_bfloat162 hp = __floats2bfloat162_rn(hn0, hn1);
            unsigned hv = *(unsigned*)&hp;
            __nv_bfloat16* dst = &g_h[wbuf][m0 + b][j0 + 2*jp];
            asm volatile("st.global.cg.u32 [%0], %1;" :: "l"(dst), "r"(hv));
        }

        // ---- group barrier: release(fence) -> arrive -> spin ----
        __threadfence();
        __syncthreads();
        if (tid == 0){
            atomicAdd(&g_barcnt[mb_*32], 1u);
            unsigned target = (unsigned)(t + 1) * NT;
            while (*(volatile unsigned*)&g_barcnt[mb_*32] < target) { __nanosleep(32); }
            __threadfence();
        }
        __syncthreads();
    }
}

// ---------------- output head: logits + softmax ----------------
__global__ void out_kernel(const float* __restrict__ W_out, float* __restrict__ out){
    int b = blockIdx.x;
    int lane = threadIdx.x;
    float acc[L_];
    #pragma unroll
    for (int l = 0; l < L_; ++l) acc[l] = 0.0f;
    for (int k = lane; k < H_; k += 32){
        float hv = __bfloat162float(g_h[0][b][k]);   // T even -> final h in buffer 0
        #pragma unroll
        for (int l = 0; l < L_; ++l) acc[l] += hv * __ldg(&W_out[l*H_ + k]);
    }
    #pragma unroll
    for (int l = 0; l < L_; ++l){
        #pragma unroll
        for (int o = 16; o; o >>= 1) acc[l] += __shfl_xor_sync(0xffffffffu, acc[l], o);
    }
    if (lane == 0){
        float mx = acc[0];
        #pragma unroll
        for (int l = 1; l < L_; ++l) mx = fmaxf(mx, acc[l]);
        float s = 0.0f;
        #pragma unroll
        for (int l = 0; l < L_; ++l){ acc[l] = expf(acc[l] - mx); s += acc[l]; }
        float inv = 1.0f / s;
        #pragma unroll
        for (int l = 0; l < L_; ++l) out[b*L_ + l] = acc[l] * inv;
    }
}

// ---------------- launch ----------------
extern "C" void kernel_launch(void* const* d_in, const int* in_sizes, int n_in,
                              void* d_out, int out_size){
    const float* x     = (const float*)d_in[0];
    const float* W_ih  = (const float*)d_in[1];
    const float* W_hh  = (const float*)d_in[2];
    const float* b     = (const float*)d_in[3];
    const float* W_out = (const float*)d_in[4];

    cudaFuncSetAttribute(lstm_scan, cudaFuncAttributeMaxDynamicSharedMemorySize, SMEM_BYTES);

    xconv_kernel<<<(B_*T_*D_/4)/256, 256>>>(x);
    pack_kernel<<<G_, 256>>>(W_ih, W_hh, b);
    init_kernel<<<256, 256>>>();
    lstm_scan<<<NBLK, THREADS, SMEM_BYTES>>>();
    out_kernel<<<B_, 32>>>(W_out, (float*)d_out);
}

// round 7
// speedup vs baseline: 2.3752x; 1.0054x over previous
#include <cuda_runtime.h>
#include <cuda_bf16.h>
#include <cstdint>

// Problem constants
#define B_ 128
#define T_ 2048
#define D_ 128
#define H_ 512
#define G_ 2048   // 4*H
#define K_ 640    // H + D
#define L_ 10

// Tiling: 4 batch groups x 32 column-tile CTAs.
// Within a CTA: 8 warps = 4 k-chunks (160) x 2 n-halves (32).
#define MT 4
#define NT 32
#define NBLK (MT*NT)
#define THREADS 256

// Smem strides (bf16 elements)
#define WS_STR 648
#define AS_STR 648

// Smem byte offsets
#define OFF_WS 0
#define OFF_AS (64*WS_STR*2)            // 82944
#define OFF_GS (OFF_AS + 32*AS_STR*2)   // 124416 : 4 slabs of [32][68] fp32
#define OFF_CS (OFF_GS + 4*32*68*4)     // 159232 : fp32 cell [32][16]
#define OFF_BS (OFF_CS + 32*16*4)       // 161280 : fp32 bias [64]
#define SMEM_BYTES (OFF_BS + 64*4)      // 161536

// Device-global scratch (all explicitly aligned — R2 lesson)
__device__ __align__(256) __nv_bfloat16 g_Wpk[G_][K_];
__device__ __align__(256) float         g_bpk[G_];
__device__ __align__(256) __nv_bfloat16 g_h[2][B_][H_];
__device__ __align__(256) __nv_bfloat16 g_xB[(size_t)B_*T_*D_];
__device__ __align__(256) unsigned      g_flag[MT*NT*32];   // per-CTA flags, 128B apart

__device__ __forceinline__ float tanhapx(float x){
    float y; asm("tanh.approx.f32 %0, %1;" : "=f"(y) : "f"(x)); return y;
}
__device__ __forceinline__ float sigm(float x){
    return fmaf(tanhapx(0.5f*x), 0.5f, 0.5f);
}

#define CPA16(dst, src) asm volatile("cp.async.cg.shared.global [%0], [%1], 16;" :: "r"(dst), "l"(src))

// ---------------- setup kernels ----------------
__global__ void xconv_kernel(const float* __restrict__ x){
    size_t i = (size_t)blockIdx.x*blockDim.x + threadIdx.x;
    float4 v = ((const float4*)x)[i];
    __nv_bfloat162* dst = (__nv_bfloat162*)g_xB;
    dst[2*i]   = __floats2bfloat162_rn(v.x, v.y);
    dst[2*i+1] = __floats2bfloat162_rn(v.z, v.w);
}

__global__ void pack_kernel(const float* __restrict__ W_ih,
                            const float* __restrict__ W_hh,
                            const float* __restrict__ b){
    int p = blockIdx.x;
    int j = p >> 2;
    int g = p & 3;
    int src = g*H_ + j;
    for (int k = threadIdx.x; k < K_; k += blockDim.x){
        float v = (k < H_) ? W_hh[src*H_ + k] : W_ih[src*D_ + (k - H_)];
        g_Wpk[p][k] = __float2bfloat16_rn(v);
    }
    if (threadIdx.x == 0) g_bpk[p] = b[src];
}

__global__ void init_kernel(){
    int i = blockIdx.x*blockDim.x + threadIdx.x;
    if (i < B_*H_) ((__nv_bfloat16*)g_h)[i] = __float2bfloat16(0.0f);
    if (i < MT*NT*32) g_flag[i] = 0u;
}

// ---------------- main persistent scan kernel ----------------
__global__ void __launch_bounds__(THREADS, 1) lstm_scan(){
    extern __shared__ char smc[];
    const uint32_t sb = (uint32_t)__cvta_generic_to_shared(smc);
    float* Gs = (float*)(smc + OFF_GS);
    float* cs = (float*)(smc + OFF_CS);
    float* bs = (float*)(smc + OFF_BS);

    const int tid = threadIdx.x;
    const int nb_ = blockIdx.x % NT;
    const int mb_ = blockIdx.x / NT;
    const int m0 = mb_ * 32;
    const int p0 = nb_ * 64;
    const int j0 = nb_ * 16;

    // Load weight slice once: 64 rows x 640 bf16 (80 float4 per row)
    {
        const float4* src = (const float4*)&g_Wpk[p0][0];
        for (int i = tid; i < 64*80; i += THREADS){
            int r = i/80, c = i%80;
            *(float4*)(smc + OFF_WS + r*WS_STR*2 + c*16) = __ldcg(src + (size_t)r*80 + c);
        }
    }
    if (tid < 64) bs[tid] = g_bpk[p0 + tid];
    for (int i = tid; i < 32*16; i += THREADS) cs[i] = 0.0f;
    __syncthreads();

    const int lane = tid & 31, warp = tid >> 5;
    const int grp = lane >> 2, tig = lane & 3;
    const int wk  = warp & 3;        // k-chunk (160 wide = 10 q-steps)
    const int wn2 = warp >> 2;       // n-half (32 cols)

    // ---- B (weight) fragments: load ONCE into registers, keep for all T steps ----
    uint32_t bf[10][2][4];
    {
        const int brow = ((lane >> 4) << 3) + (lane & 7);
        const int bcol8 = ((lane >> 3) & 1) * 8;
        #pragma unroll
        for (int q = 0; q < 10; ++q)
            #pragma unroll
            for (int nn = 0; nn < 2; ++nn){
                uint32_t addr = sb + OFF_WS +
                    (uint32_t)(((wn2*32 + nn*16 + brow)*WS_STR + wk*160 + q*16 + bcol8)*2);
                asm volatile("ldmatrix.sync.aligned.m8n8.x4.shared.b16 {%0,%1,%2,%3}, [%4];"
                    : "=r"(bf[q][nn][0]),"=r"(bf[q][nn][1]),"=r"(bf[q][nn][2]),"=r"(bf[q][nn][3])
                    : "r"(addr));
            }
    }

    // A-fragment ldmatrix base addresses
    uint32_t aBase[2];
    #pragma unroll
    for (int mh = 0; mh < 2; ++mh)
        aBase[mh] = sb + OFF_AS +
            (uint32_t)(((mh*16 + (lane & 15))*AS_STR + (lane >> 4)*8)*2);

    // This CTA's flag + the flag this lane polls (lane l watches producer l)
    unsigned* myFlag   = &g_flag[(mb_*NT + nb_)*32];
    const unsigned* poFlag = &g_flag[(mb_*NT + lane)*32];

    for (int t = 0; t < T_; ++t){
        // ---- bulk load A tile via cp.async: h (32x512) + x (32x128) ----
        {
            const __nv_bfloat16* hsrc = &g_h[t & 1][m0][0];
            #pragma unroll
            for (int i = 0; i < 8; ++i){
                int s = tid + i*THREADS;
                int r = s >> 6, c = s & 63;
                CPA16(sb + OFF_AS + (uint32_t)(r*AS_STR*2 + c*16), hsrc + r*H_ + c*8);
            }
            const __nv_bfloat16* xsrc = g_xB + ((size_t)m0*T_ + t)*D_;
            #pragma unroll
            for (int i = 0; i < 2; ++i){
                int s = tid + i*THREADS;
                int r = s >> 4, c = s & 15;
                CPA16(sb + OFF_AS + (uint32_t)(r*AS_STR*2 + 1024 + c*16),
                      xsrc + (size_t)r*T_*D_ + c*8);
            }
            asm volatile("cp.async.commit_group;");
            asm volatile("cp.async.wait_group 0;");
        }
        __syncthreads();

        // ---- MMA: m32 x n32 x k160 per warp; A frags double-buffered ----
        float acc[2][4][4] = {};
        {
            const uint32_t kbase = (uint32_t)(wk*320);
            uint32_t a[2][2][4];
            #pragma unroll
            for (int mh = 0; mh < 2; ++mh)
                asm volatile("ldmatrix.sync.aligned.m8n8.x4.shared.b16 {%0,%1,%2,%3}, [%4];"
                    : "=r"(a[0][mh][0]),"=r"(a[0][mh][1]),"=r"(a[0][mh][2]),"=r"(a[0][mh][3])
                    : "r"(aBase[mh] + kbase));
            #pragma unroll
            for (int q = 0; q < 10; ++q){
                const int cur = q & 1, nxt = cur ^ 1;
                if (q < 9){
                    #pragma unroll
                    for (int mh = 0; mh < 2; ++mh)
                        asm volatile("ldmatrix.sync.aligned.m8n8.x4.shared.b16 {%0,%1,%2,%3}, [%4];"
                            : "=r"(a[nxt][mh][0]),"=r"(a[nxt][mh][1]),
                              "=r"(a[nxt][mh][2]),"=r"(a[nxt][mh][3])
                            : "r"(aBase[mh] + kbase + (q+1)*32));
                }
                #pragma unroll
                for (int mh = 0; mh < 2; ++mh)
                    #pragma unroll
                    for (int nn = 0; nn < 2; ++nn){
                        float* A0 = acc[mh][2*nn];
                        float* A1 = acc[mh][2*nn + 1];
                        asm("mma.sync.aligned.m16n8k16.row.col.f32.bf16.bf16.f32 "
                            "{%0,%1,%2,%3}, {%4,%5,%6,%7}, {%8,%9}, {%0,%1,%2,%3};"
                            : "+f"(A0[0]),"+f"(A0[1]),"+f"(A0[2]),"+f"(A0[3])
                            : "r"(a[cur][mh][0]),"r"(a[cur][mh][1]),
                              "r"(a[cur][mh][2]),"r"(a[cur][mh][3]),
                              "r"(bf[q][nn][0]),"r"(bf[q][nn][1]));
                        asm("mma.sync.aligned.m16n8k16.row.col.f32.bf16.bf16.f32 "
                            "{%0,%1,%2,%3}, {%4,%5,%6,%7}, {%8,%9}, {%0,%1,%2,%3};"
                            : "+f"(A1[0]),"+f"(A1[1]),"+f"(A1[2]),"+f"(A1[3])
                            : "r"(a[cur][mh][0]),"r"(a[cur][mh][1]),
                              "r"(a[cur][mh][2]),"r"(a[cur][mh][3]),
                              "r"(bf[q][nn][2]),"r"(bf[q][nn][3]));
                    }
            }
        }

        // ---- scatter partial gates to slab[wk] ----
        {
            float* Gw = Gs + wk*(32*68);
            #pragma unroll
            for (int mh = 0; mh < 2; ++mh){
                int r0 = (mh*16 + grp)*68, r1 = r0 + 8*68;
                #pragma unroll
                for (int nn = 0; nn < 2; ++nn)
                    #pragma unroll
                    for (int hi = 0; hi < 2; ++hi){
                        int c = wn2*32 + nn*16 + hi*8 + 2*tig;
                        float* A = acc[mh][2*nn + hi];
                        *(float2*)&Gw[r0 + c] = make_float2(A[0], A[1]);
                        *(float2*)&Gw[r1 + c] = make_float2(A[2], A[3]);
                    }
            }
        }
        __syncthreads();

        // ---- reduce 4 k-partials + LSTM cell update (2 pairs per thread) ----
        const int wbuf = (t + 1) & 1;
        {
            int b  = tid >> 3;
            int jp = tid & 7;               // jj pair: 2*jp, 2*jp+1
            float4 s0 = *(const float4*)&bs[8*jp];
            float4 s1 = *(const float4*)&bs[8*jp + 4];
            #pragma unroll
            for (int w = 0; w < 4; ++w){
                const float* base = &Gs[w*(32*68) + b*68 + 8*jp];
                float4 v0 = *(const float4*)(base);
                float4 v1 = *(const float4*)(base + 4);
                s0.x += v0.x; s0.y += v0.y; s0.z += v0.z; s0.w += v0.w;
                s1.x += v1.x; s1.y += v1.y; s1.z += v1.z; s1.w += v1.w;
            }
            float c0 = cs[b*16 + 2*jp], c1 = cs[b*16 + 2*jp + 1];
            float cn0 = sigm(s0.y)*c0 + sigm(s0.x)*tanhapx(s0.z);
            float cn1 = sigm(s1.y)*c1 + sigm(s1.x)*tanhapx(s1.z);
            float hn0 = sigm(s0.w)*tanhapx(cn0);
            float hn1 = sigm(s1.w)*tanhapx(cn1);
            cs[b*16 + 2*jp]     = cn0;
            cs[b*16 + 2*jp + 1] = cn1;
            __nv_bfloat162 hp = __floats2bfloat162_rn(hn0, hn1);
            unsigned hv = *(unsigned*)&hp;
            __nv_bfloat16* dst = &g_h[wbuf][m0 + b][j0 + 2*jp];
            asm volatile("st.global.cg.u32 [%0], %1;" :: "l"(dst), "r"(hv));
        }

        // ---- flag barrier: one release-store, 32 parallel acquire-polls ----
        __syncthreads();                    // all h-stores of this CTA issued
        if (tid == 0){
            asm volatile("st.global.release.gpu.u32 [%0], %1;"
                         :: "l"(myFlag), "r"((unsigned)(t + 1)));
        }
        if (warp == 0){
            unsigned v;
            do {
                asm volatile("ld.global.acquire.gpu.u32 %0, [%1];" : "=r"(v) : "l"(poFlag));
            } while (v < (unsigned)(t + 1));
        }
        __syncthreads();
    }
}

// ---------------- output head: logits + softmax ----------------
__global__ void out_kernel(const float* __restrict__ W_out, float* __restrict__ out){
    int b = blockIdx.x;
    int lane = threadIdx.x;
    float acc[L_];
    #pragma unroll
    for (int l = 0; l < L_; ++l) acc[l] = 0.0f;
    for (int k = lane; k < H_; k += 32){
        float hv = __bfloat162float(g_h[0][b][k]);   // T even -> final h in buffer 0
        #pragma unroll
        for (int l = 0; l < L_; ++l) acc[l] += hv * __ldg(&W_out[l*H_ + k]);
    }
    #pragma unroll
    for (int l = 0; l < L_; ++l){
        #pragma unroll
        for (int o = 16; o; o >>= 1) acc[l] += __shfl_xor_sync(0xffffffffu, acc[l], o);
    }
    if (lane == 0){
        float mx = acc[0];
        #pragma unroll
        for (int l = 1; l < L_; ++l) mx = fmaxf(mx, acc[l]);
        float s = 0.0f;
        #pragma unroll
        for (int l = 0; l < L_; ++l){ acc[l] = expf(acc[l] - mx); s += acc[l]; }
        float inv = 1.0f / s;
        #pragma unroll
        for (int l = 0; l < L_; ++l) out[b*L_ + l] = acc[l] * inv;
    }
}

// ---------------- launch ----------------
extern "C" void kernel_launch(void* const* d_in, const int* in_sizes, int n_in,
                              void* d_out, int out_size){
    const float* x     = (const float*)d_in[0];
    const float* W_ih  = (const float*)d_in[1];
    const float* W_hh  = (const float*)d_in[2];
    const float* b     = (const float*)d_in[3];
    const float* W_out = (const float*)d_in[4];

    cudaFuncSetAttribute(lstm_scan, cudaFuncAttributeMaxDynamicSharedMemorySize, SMEM_BYTES);

    xconv_kernel<<<(B_*T_*D_/4)/256, 256>>>(x);
    pack_kernel<<<G_, 256>>>(W_ih, W_hh, b);
    init_kernel<<<256, 256>>>();
    lstm_scan<<<NBLK, THREADS, SMEM_BYTES>>>();
    out_kernel<<<B_, 32>>>(W_out, (float*)d_out);
}